// round 1
// baseline (speedup 1.0000x reference)
#include <cuda_runtime.h>
#include <math.h>

#define NN 50000
#define NE 600000

// ---------------- scratch (static device allocations; no cudaMalloc) --------
__device__ int   g_is64;
__device__ int   g_src[NE];
__device__ int   g_dst[NE];
__device__ int   g_deg[NN];
__device__ float g_dinv[NN];
__device__ int   g_rowptr[NN + 1];
__device__ int   g_rowcur[NN];
__device__ int   g_csr_src[NE];
__device__ float g_csr_norm[NE];
__device__ float g_aggx[(size_t)NN * 128];
__device__ float g_h1  [(size_t)NN * 256];
__device__ float g_t2  [(size_t)NN * 128];
__device__ float g_h2  [(size_t)NN * 128];
__device__ float g_t3  [(size_t)NN * 2];

// ---------------- graph preprocessing ---------------------------------------

// Detect whether edge_index is int64 or int32 (JAX may silently downcast).
// If int64 (little-endian), the high 32-bit word of every element is 0
// (values in [0, 50000)). Check first 1000 entries: reads stay within the
// int32-sized buffer too (2000 ints < 1.2M ints).
__global__ void k_detect(const int* __restrict__ e32) {
    __shared__ int s;
    if (threadIdx.x == 0) s = 0;
    __syncthreads();
    int nz = 0;
    for (int i = threadIdx.x; i < 1000; i += blockDim.x)
        if (e32[2 * i + 1] != 0) nz = 1;
    if (nz) atomicExch(&s, 1);
    __syncthreads();
    if (threadIdx.x == 0) g_is64 = (s == 0) ? 1 : 0;
}

__global__ void k_initdeg() {
    int i = blockIdx.x * blockDim.x + threadIdx.x;
    if (i < NN) g_deg[i] = 1;  // self-loop
}

__global__ void k_convert(const void* __restrict__ e) {
    int i = blockIdx.x * blockDim.x + threadIdx.x;
    if (i >= NE) return;
    int s, d;
    if (g_is64) {
        const long long* p = (const long long*)e;
        s = (int)p[i];
        d = (int)p[NE + i];
    } else {
        const int* p = (const int*)e;
        s = p[i];
        d = p[NE + i];
    }
    g_src[i] = s;
    g_dst[i] = d;
    atomicAdd(&g_deg[d], 1);
}

__global__ void k_dinv() {
    int i = blockIdx.x * blockDim.x + threadIdx.x;
    if (i < NN) g_dinv[i] = rsqrtf((float)g_deg[i]);
}

// Single-block exclusive scan of (deg-1) over 50000 nodes -> rowptr/rowcur.
__global__ void k_scan() {
    __shared__ int sh[1024];
    __shared__ int carry;
    if (threadIdx.x == 0) carry = 0;
    __syncthreads();
    for (int base = 0; base < NN; base += 1024) {
        int i = base + threadIdx.x;
        int v = (i < NN) ? (g_deg[i] - 1) : 0;
        sh[threadIdx.x] = v;
        __syncthreads();
        for (int off = 1; off < 1024; off <<= 1) {
            int t = (threadIdx.x >= off) ? sh[threadIdx.x - off] : 0;
            __syncthreads();
            sh[threadIdx.x] += t;
            __syncthreads();
        }
        if (i < NN) {
            int excl = carry + sh[threadIdx.x] - v;
            g_rowptr[i] = excl;
            g_rowcur[i] = excl;
        }
        __syncthreads();
        if (threadIdx.x == 0) carry += sh[1023];
        __syncthreads();
    }
    if (threadIdx.x == 0) g_rowptr[NN] = NE;
}

__global__ void k_scatter() {
    int e = blockIdx.x * blockDim.x + threadIdx.x;
    if (e >= NE) return;
    int d = g_dst[e];
    int s = g_src[e];
    int pos = atomicAdd(&g_rowcur[d], 1);
    g_csr_src[pos] = s;
    g_csr_norm[pos] = g_dinv[s] * g_dinv[d];
}

// ---------------- aggregation (gather-only, warp per node, D=128) -----------
template <int EPI>  // EPI=1: out = relu(agg + bias)
__global__ void k_agg128(const float* __restrict__ in, float* __restrict__ out,
                         const float* __restrict__ bias) {
    int node = (blockIdx.x * blockDim.x + threadIdx.x) >> 5;
    if (node >= NN) return;
    int lane = threadIdx.x & 31;
    float di = g_dinv[node];
    float sl = di * di;  // self-loop norm
    float4 acc = __ldg((const float4*)(in + (size_t)node * 128) + lane);
    acc.x *= sl; acc.y *= sl; acc.z *= sl; acc.w *= sl;
    int beg = g_rowptr[node], end = g_rowptr[node + 1];
    for (int e = beg; e < end; e++) {
        int s = g_csr_src[e];
        float w = g_csr_norm[e];
        float4 v = __ldg((const float4*)(in + (size_t)s * 128) + lane);
        acc.x = fmaf(w, v.x, acc.x);
        acc.y = fmaf(w, v.y, acc.y);
        acc.z = fmaf(w, v.z, acc.z);
        acc.w = fmaf(w, v.w, acc.w);
    }
    if (EPI) {
        float4 b = ((const float4*)bias)[lane];
        acc.x = fmaxf(acc.x + b.x, 0.f);
        acc.y = fmaxf(acc.y + b.y, 0.f);
        acc.z = fmaxf(acc.z + b.z, 0.f);
        acc.w = fmaxf(acc.w + b.w, 0.f);
    }
    ((float4*)(out + (size_t)node * 128))[lane] = acc;
}

// ---------------- tiled SGEMM: C[M,N] = A[M,K] @ B[K,N] (+bias, relu) -------
// 64x64 block tile, BK=16, 256 threads, 4x4 micro-tile, float4 smem reads.
template <bool RELU_BIAS>
__global__ void __launch_bounds__(256)
k_gemm64(const float* __restrict__ A, const float* __restrict__ B,
         const float* __restrict__ bias, float* __restrict__ C,
         int M, int K, int N) {
    __shared__ float As[16][68];  // transposed A tile, padded (272B rows, 16B-aligned)
    __shared__ float Bs[16][64];
    int tid = threadIdx.x;
    int m0 = blockIdx.y * 64;
    int n0 = blockIdx.x * 64;
    int aRow = tid >> 2, aKq = tid & 3;
    int bK = tid >> 4, bNq = tid & 15;
    int ty = tid >> 4, tx = tid & 15;

    float acc[4][4];
#pragma unroll
    for (int i = 0; i < 4; i++)
#pragma unroll
        for (int j = 0; j < 4; j++) acc[i][j] = 0.f;

    for (int k0 = 0; k0 < K; k0 += 16) {
        float4 a = make_float4(0.f, 0.f, 0.f, 0.f);
        int m = m0 + aRow;
        if (m < M) a = *(const float4*)(A + (size_t)m * K + k0 + 4 * aKq);
        As[4 * aKq + 0][aRow] = a.x;
        As[4 * aKq + 1][aRow] = a.y;
        As[4 * aKq + 2][aRow] = a.z;
        As[4 * aKq + 3][aRow] = a.w;
        float4 b = *(const float4*)(B + (size_t)(k0 + bK) * N + n0 + 4 * bNq);
        *(float4*)&Bs[bK][4 * bNq] = b;
        __syncthreads();
#pragma unroll
        for (int kk = 0; kk < 16; kk++) {
            float4 av = *(const float4*)&As[kk][ty * 4];
            float4 bv = *(const float4*)&Bs[kk][tx * 4];
            acc[0][0] = fmaf(av.x, bv.x, acc[0][0]);
            acc[0][1] = fmaf(av.x, bv.y, acc[0][1]);
            acc[0][2] = fmaf(av.x, bv.z, acc[0][2]);
            acc[0][3] = fmaf(av.x, bv.w, acc[0][3]);
            acc[1][0] = fmaf(av.y, bv.x, acc[1][0]);
            acc[1][1] = fmaf(av.y, bv.y, acc[1][1]);
            acc[1][2] = fmaf(av.y, bv.z, acc[1][2]);
            acc[1][3] = fmaf(av.y, bv.w, acc[1][3]);
            acc[2][0] = fmaf(av.z, bv.x, acc[2][0]);
            acc[2][1] = fmaf(av.z, bv.y, acc[2][1]);
            acc[2][2] = fmaf(av.z, bv.z, acc[2][2]);
            acc[2][3] = fmaf(av.z, bv.w, acc[2][3]);
            acc[3][0] = fmaf(av.w, bv.x, acc[3][0]);
            acc[3][1] = fmaf(av.w, bv.y, acc[3][1]);
            acc[3][2] = fmaf(av.w, bv.z, acc[3][2]);
            acc[3][3] = fmaf(av.w, bv.w, acc[3][3]);
        }
        __syncthreads();
    }

#pragma unroll
    for (int i = 0; i < 4; i++) {
        int m = m0 + ty * 4 + i;
        if (m >= M) continue;
        float4 c = make_float4(acc[i][0], acc[i][1], acc[i][2], acc[i][3]);
        if (RELU_BIAS) {
            float4 b = *(const float4*)(bias + n0 + tx * 4);
            c.x = fmaxf(c.x + b.x, 0.f);
            c.y = fmaxf(c.y + b.y, 0.f);
            c.z = fmaxf(c.z + b.z, 0.f);
            c.w = fmaxf(c.w + b.w, 0.f);
        }
        *(float4*)(C + (size_t)m * N + n0 + tx * 4) = c;
    }
}

// ---------------- layer-3 GEMM: [N,128] @ [128,2], warp per node ------------
__global__ void k_gemm3(const float* __restrict__ A, const float* __restrict__ W,
                        float* __restrict__ C) {
    __shared__ float w[256];
    if (threadIdx.x < 256) w[threadIdx.x] = W[threadIdx.x];
    __syncthreads();
    int node = (blockIdx.x * blockDim.x + threadIdx.x) >> 5;
    int lane = threadIdx.x & 31;
    if (node >= NN) return;
    float4 v = *(const float4*)(A + (size_t)node * 128 + lane * 4);
    float a0 = v.x * w[8 * lane + 0] + v.y * w[8 * lane + 2] +
               v.z * w[8 * lane + 4] + v.w * w[8 * lane + 6];
    float a1 = v.x * w[8 * lane + 1] + v.y * w[8 * lane + 3] +
               v.z * w[8 * lane + 5] + v.w * w[8 * lane + 7];
#pragma unroll
    for (int o = 16; o > 0; o >>= 1) {
        a0 += __shfl_xor_sync(0xffffffffu, a0, o);
        a1 += __shfl_xor_sync(0xffffffffu, a1, o);
    }
    if (lane == 0) {
        C[2 * (size_t)node + 0] = a0;
        C[2 * (size_t)node + 1] = a1;
    }
}

// ---------------- layer-3 aggregation (D=2) + bias + log_softmax ------------
__global__ void k_agg2_lsm(const float* __restrict__ in, float* __restrict__ out,
                           const float* __restrict__ b3) {
    int i = blockIdx.x * blockDim.x + threadIdx.x;
    if (i >= NN) return;
    float di = g_dinv[i];
    float sl = di * di;
    float2 v = *(const float2*)(in + 2 * (size_t)i);
    float a0 = sl * v.x, a1 = sl * v.y;
    int beg = g_rowptr[i], end = g_rowptr[i + 1];
    for (int e = beg; e < end; e++) {
        int s = g_csr_src[e];
        float w = g_csr_norm[e];
        float2 u = *(const float2*)(in + 2 * (size_t)s);
        a0 = fmaf(w, u.x, a0);
        a1 = fmaf(w, u.y, a1);
    }
    a0 += b3[0];
    a1 += b3[1];
    float m = fmaxf(a0, a1);
    float lse = m + logf(expf(a0 - m) + expf(a1 - m));
    out[2 * (size_t)i + 0] = a0 - lse;
    out[2 * (size_t)i + 1] = a1 - lse;
}

// ---------------- launch -----------------------------------------------------
extern "C" void kernel_launch(void* const* d_in, const int* in_sizes, int n_in,
                              void* d_out, int out_size) {
    const float* x  = (const float*)d_in[0];
    const float* W1 = (const float*)d_in[1];
    const float* b1 = (const float*)d_in[2];
    const float* W2 = (const float*)d_in[3];
    const float* b2 = (const float*)d_in[4];
    const float* W3 = (const float*)d_in[5];
    const float* b3 = (const float*)d_in[6];
    const void*  ei = d_in[7];
    float* out = (float*)d_out;

    void* p;
    cudaGetSymbolAddress(&p, g_aggx); float* aggx = (float*)p;
    cudaGetSymbolAddress(&p, g_h1);   float* h1   = (float*)p;
    cudaGetSymbolAddress(&p, g_t2);   float* t2   = (float*)p;
    cudaGetSymbolAddress(&p, g_h2);   float* h2   = (float*)p;
    cudaGetSymbolAddress(&p, g_t3);   float* t3   = (float*)p;

    // graph preprocessing: degrees, normalization, CSR (sorted-by-dst)
    k_detect<<<1, 256>>>((const int*)ei);
    k_initdeg<<<(NN + 255) / 256, 256>>>();
    k_convert<<<(NE + 255) / 256, 256>>>(ei);
    k_dinv<<<(NN + 255) / 256, 256>>>();
    k_scan<<<1, 1024>>>();
    k_scatter<<<(NE + 255) / 256, 256>>>();

    const int aggBlocks = (NN * 32 + 255) / 256;  // warp per node, 8 warps/block

    // Layer 1: agg(x) -> @W1 + b1, relu
    k_agg128<0><<<aggBlocks, 256>>>(x, aggx, nullptr);
    k_gemm64<true><<<dim3(256 / 64, (NN + 63) / 64), 256>>>(aggx, W1, b1, h1, NN, 128, 256);

    // Layer 2: h1@W2 -> agg -> +b2, relu
    k_gemm64<false><<<dim3(128 / 64, (NN + 63) / 64), 256>>>(h1, W2, nullptr, t2, NN, 256, 128);
    k_agg128<1><<<aggBlocks, 256>>>(t2, h2, b2);

    // Layer 3: h2@W3 -> agg -> +b3 -> log_softmax
    k_gemm3<<<aggBlocks, 256>>>(h2, W3, t3);
    k_agg2_lsm<<<(NN + 255) / 256, 256>>>(t3, out, b3);
}

// round 7
// speedup vs baseline: 1.3310x; 1.3310x over previous
#include <cuda_runtime.h>
#include <cuda_bf16.h>
#include <math.h>
#include <stdint.h>

#define NN 50000
#define NP 50048   // 391 * 128, padded M
#define NE 600000
#define NCHUNK 49  // ceil(NN/1024)

// ---------------- scratch (static device globals; zero-initialized) ---------
__device__ int   g_is64;
__device__ int   g_src[NE];
__device__ int   g_dst[NE];
__device__ int   g_deg[NN];
__device__ float g_dinv[NN];
__device__ int   g_rowptr[NN + 1];
__device__ int   g_rowcur[NN];
__device__ int   g_psum[NCHUNK];
__device__ int   g_csr_src[NE];
__device__ float g_csr_norm[NE];

__device__ __nv_bfloat16 g_axh[(size_t)NP * 128];
__device__ __nv_bfloat16 g_axl[(size_t)NP * 128];
__device__ __nv_bfloat16 g_h1h[(size_t)NP * 256];
__device__ __nv_bfloat16 g_h1l[(size_t)NP * 256];
__device__ float g_t2[(size_t)NP * 128];
__device__ float g_t3[(size_t)NN * 2];
__device__ __nv_bfloat16 g_w1h[256 * 128], g_w1l[256 * 128];   // W1^T hi/lo [N=256][K=128]
__device__ __nv_bfloat16 g_w2h[128 * 256], g_w2l[128 * 256];   // W2^T hi/lo [N=128][K=256]

// ---------------- small PTX helpers (all <= sm_80 features) ------------------
__device__ __forceinline__ uint32_t smem_u32(const void* p) {
    uint32_t a;
    asm("{ .reg .u64 t; cvta.to.shared.u64 t, %1; cvt.u32.u64 %0, t; }" : "=r"(a) : "l"(p));
    return a;
}
__device__ __forceinline__ void cp16(uint32_t dst, const void* src) {
    asm volatile("cp.async.cg.shared.global [%0], [%1], 16;" :: "r"(dst), "l"(src));
}
#define CP_COMMIT() asm volatile("cp.async.commit_group;" ::: "memory")
#define CP_WAIT0()  asm volatile("cp.async.wait_group 0;" ::: "memory")
#define CP_WAIT1()  asm volatile("cp.async.wait_group 1;" ::: "memory")

#define LDM_X4(r0, r1, r2, r3, a) \
    asm volatile("ldmatrix.sync.aligned.m8n8.x4.shared.b16 {%0,%1,%2,%3}, [%4];" \
                 : "=r"(r0), "=r"(r1), "=r"(r2), "=r"(r3) : "r"(a))

#define MMA_BF16(C, A, B) \
    asm volatile("mma.sync.aligned.m16n8k16.row.col.f32.bf16.bf16.f32 " \
                 "{%0,%1,%2,%3},{%4,%5,%6,%7},{%8,%9},{%0,%1,%2,%3};" \
                 : "+f"((C)[0]), "+f"((C)[1]), "+f"((C)[2]), "+f"((C)[3]) \
                 : "r"((A)[0]), "r"((A)[1]), "r"((A)[2]), "r"((A)[3]), \
                   "r"((B)[0]), "r"((B)[1]))

// ---------------- graph preprocessing ---------------------------------------
__global__ void k_detect(const int* __restrict__ e32) {
    __shared__ int s;
    if (threadIdx.x == 0) s = 0;
    __syncthreads();
    int nz = 0;
    for (int i = threadIdx.x; i < 1000; i += blockDim.x)
        if (e32[2 * i + 1] != 0) nz = 1;
    if (nz) atomicExch(&s, 1);
    __syncthreads();
    if (threadIdx.x == 0) g_is64 = (s == 0) ? 1 : 0;
}

__global__ void k_initdeg() {
    int i = blockIdx.x * blockDim.x + threadIdx.x;
    if (i < NN) g_deg[i] = 1;  // self-loop
}

__global__ void k_convert(const void* __restrict__ e) {
    int i = blockIdx.x * blockDim.x + threadIdx.x;
    if (i >= NE) return;
    int s, d;
    if (g_is64) {
        const long long* p = (const long long*)e;
        s = (int)p[i];
        d = (int)p[NE + i];
    } else {
        const int* p = (const int*)e;
        s = p[i];
        d = p[NE + i];
    }
    g_src[i] = s;
    g_dst[i] = d;
    atomicAdd(&g_deg[d], 1);
}

__global__ void k_dinv() {
    int i = blockIdx.x * blockDim.x + threadIdx.x;
    if (i < NN) g_dinv[i] = rsqrtf((float)g_deg[i]);
}

// parallel 3-stage exclusive scan of (deg-1) -> rowptr
__global__ void k_scan1() {
    __shared__ int sh[1024];
    int b = blockIdx.x;
    int i = b * 1024 + threadIdx.x;
    int v = (i < NN) ? (g_deg[i] - 1) : 0;
    sh[threadIdx.x] = v;
    __syncthreads();
    for (int off = 1; off < 1024; off <<= 1) {
        int t = (threadIdx.x >= off) ? sh[threadIdx.x - off] : 0;
        __syncthreads();
        sh[threadIdx.x] += t;
        __syncthreads();
    }
    if (i < NN) g_rowptr[i] = sh[threadIdx.x] - v;  // local exclusive
    if (threadIdx.x == 1023) g_psum[b] = sh[1023];
}
__global__ void k_scan2() {
    if (threadIdx.x == 0) {
        int run = 0;
        for (int b = 0; b < NCHUNK; b++) {
            int t = g_psum[b];
            g_psum[b] = run;
            run += t;
        }
        g_rowptr[NN] = NE;
    }
}
__global__ void k_scan3() {
    int i = blockIdx.x * blockDim.x + threadIdx.x;
    if (i >= NN) return;
    int r = g_rowptr[i] + g_psum[i >> 10];
    g_rowptr[i] = r;
    g_rowcur[i] = r;
}

__global__ void k_scatter() {
    int e = blockIdx.x * blockDim.x + threadIdx.x;
    if (e >= NE) return;
    int d = g_dst[e];
    int s = g_src[e];
    int pos = atomicAdd(&g_rowcur[d], 1);
    g_csr_src[pos] = s;
    g_csr_norm[pos] = g_dinv[s] * g_dinv[d];
}

// ---------------- weight transpose + bf16 hi/lo split ------------------------
__global__ void k_wsplit(const float* __restrict__ W, __nv_bfloat16* __restrict__ Th,
                         __nv_bfloat16* __restrict__ Tl, int K, int N) {
    int i = blockIdx.x * blockDim.x + threadIdx.x;
    if (i >= K * N) return;
    int k = i / N, n = i % N;
    float v = W[i];
    __nv_bfloat16 h = __float2bfloat16(v);
    float r = v - __bfloat162float(h);
    Th[n * K + k] = h;
    Tl[n * K + k] = __float2bfloat16(r);
}

// ---------------- layer-2 aggregation + bias/relu + fused W3 projection -----
// in = t2 [NN,128] fp32; out = t3 [NN,2] (node's h2 dot W3 columns).
__global__ void k_agg128_g3(const float* __restrict__ in, float* __restrict__ out,
                            const float* __restrict__ bias, const float* __restrict__ W3) {
    __shared__ float w[256];
    if (threadIdx.x < 256) w[threadIdx.x] = W3[threadIdx.x];
    __syncthreads();
    int node = (blockIdx.x * blockDim.x + threadIdx.x) >> 5;
    if (node >= NN) return;
    int lane = threadIdx.x & 31;
    float di = g_dinv[node];
    float sl = di * di;
    float4 acc = __ldg((const float4*)(in + (size_t)node * 128) + lane);
    acc.x *= sl; acc.y *= sl; acc.z *= sl; acc.w *= sl;
    int beg = g_rowptr[node], end = g_rowptr[node + 1];
    for (int e = beg; e < end; e++) {
        int s = g_csr_src[e];
        float wgt = g_csr_norm[e];
        float4 v = __ldg((const float4*)(in + (size_t)s * 128) + lane);
        acc.x = fmaf(wgt, v.x, acc.x);
        acc.y = fmaf(wgt, v.y, acc.y);
        acc.z = fmaf(wgt, v.z, acc.z);
        acc.w = fmaf(wgt, v.w, acc.w);
    }
    float4 b = ((const float4*)bias)[lane];
    acc.x = fmaxf(acc.x + b.x, 0.f);
    acc.y = fmaxf(acc.y + b.y, 0.f);
    acc.z = fmaxf(acc.z + b.z, 0.f);
    acc.w = fmaxf(acc.w + b.w, 0.f);
    // fused h2 @ W3 (dims 4*lane+j -> w[8*lane+2j+o])
    float a0 = acc.x * w[8 * lane + 0] + acc.y * w[8 * lane + 2] +
               acc.z * w[8 * lane + 4] + acc.w * w[8 * lane + 6];
    float a1 = acc.x * w[8 * lane + 1] + acc.y * w[8 * lane + 3] +
               acc.z * w[8 * lane + 5] + acc.w * w[8 * lane + 7];
#pragma unroll
    for (int o = 16; o > 0; o >>= 1) {
        a0 += __shfl_xor_sync(0xffffffffu, a0, o);
        a1 += __shfl_xor_sync(0xffffffffu, a1, o);
    }
    if (lane == 0) {
        out[2 * (size_t)node + 0] = a0;
        out[2 * (size_t)node + 1] = a1;
    }
}

// ---------------- layer-1 input aggregation -> bf16 hi/lo split --------------
__global__ void k_agg128_split(const float* __restrict__ in, __nv_bfloat16* __restrict__ oh,
                               __nv_bfloat16* __restrict__ ol) {
    int node = (blockIdx.x * blockDim.x + threadIdx.x) >> 5;
    if (node >= NN) return;
    int lane = threadIdx.x & 31;
    float di = g_dinv[node];
    float sl = di * di;
    float4 acc = __ldg((const float4*)(in + (size_t)node * 128) + lane);
    acc.x *= sl; acc.y *= sl; acc.z *= sl; acc.w *= sl;
    int beg = g_rowptr[node], end = g_rowptr[node + 1];
    for (int e = beg; e < end; e++) {
        int s = g_csr_src[e];
        float w = g_csr_norm[e];
        float4 v = __ldg((const float4*)(in + (size_t)s * 128) + lane);
        acc.x = fmaf(w, v.x, acc.x);
        acc.y = fmaf(w, v.y, acc.y);
        acc.z = fmaf(w, v.z, acc.z);
        acc.w = fmaf(w, v.w, acc.w);
    }
    float a[4] = {acc.x, acc.y, acc.z, acc.w};
    unsigned short hs[4], ls[4];
#pragma unroll
    for (int j = 0; j < 4; j++) {
        __nv_bfloat16 h = __float2bfloat16(a[j]);
        float r = a[j] - __bfloat162float(h);
        hs[j] = __bfloat16_as_ushort(h);
        ls[j] = __bfloat16_as_ushort(__float2bfloat16(r));
    }
    size_t off = (size_t)node * 128 + lane * 4;
    *(uint2*)(oh + off) = make_uint2((uint32_t)hs[0] | ((uint32_t)hs[1] << 16),
                                     (uint32_t)hs[2] | ((uint32_t)hs[3] << 16));
    *(uint2*)(ol + off) = make_uint2((uint32_t)ls[0] | ((uint32_t)ls[1] << 16),
                                     (uint32_t)ls[2] | ((uint32_t)ls[3] << 16));
}

// ---------------- split-bf16 HMMA GEMM ---------------------------------------
// C[M,N] = (Ah+Al)[M,K] @ (Bh+Bl)^T with B stored [N][K] row-major.
// 3-term product (hh + hl + lh). BM=128, BN=128, BK=32, 256 threads, 8 warps
// in 4(m) x 2(n); warp tile 32x64 = 2x8 m16n8k16 fragments. cp.async double
// buffer. No bounds checks: M padded to a multiple of 128, pad rows are zero.
// EPI=0: fp32 out. EPI=1: bf16 hi/lo of relu(C + bias).
#define SROW 80        // bytes per smem row (32 bf16 + 16B pad)
#define SBUF 10240     // 128 rows * 80B, one matrix, one stage
#define SSTAGE 40960   // 4 matrices
#define SMEM_TOTAL 81920

template <int K, int N, int EPI>
__global__ void __launch_bounds__(256)
k_hmma(const __nv_bfloat16* __restrict__ Ah, const __nv_bfloat16* __restrict__ Al,
       const __nv_bfloat16* __restrict__ Bh, const __nv_bfloat16* __restrict__ Bl,
       const float* __restrict__ bias, float* __restrict__ outF,
       __nv_bfloat16* __restrict__ outH, __nv_bfloat16* __restrict__ outL) {
    extern __shared__ char smem[];
    const uint32_t sb = smem_u32(smem);
    const int tid = threadIdx.x;
    const int lane = tid & 31;
    const int warp = tid >> 5;
    const int wm = warp & 3;   // 32-row block
    const int wn = warp >> 2;  // 64-col block
    const int m0 = blockIdx.y * 128;
    const int n0 = blockIdx.x * 128;

    const __nv_bfloat16* gsrc[4] = {Ah, Al, Bh, Bl};

    float acc[2][8][4];
#pragma unroll
    for (int i = 0; i < 2; i++)
#pragma unroll
        for (int j = 0; j < 8; j++)
#pragma unroll
            for (int c = 0; c < 4; c++) acc[i][j][c] = 0.f;

    // --- stage loader: 2048 x 16B chunks (A hi/lo, B hi/lo), 8 per thread ---
    auto load_stage = [&](int stage, int kk0) {
#pragma unroll
        for (int j = 0; j < 8; j++) {
            int c = tid + j * 256;
            int which = c >> 9;          // 0:Ah 1:Al 2:Bh 3:Bl
            int cc = c & 511;
            int row = cc >> 2, kc = cc & 3;
            int grow = (which < 2) ? (m0 + row) : (n0 + row);
            const __nv_bfloat16* src = gsrc[which] + (size_t)grow * K + kk0 + kc * 8;
            uint32_t dst = sb + stage * SSTAGE + which * SBUF + row * SROW + kc * 16;
            cp16(dst, src);
        }
    };

    load_stage(0, 0);
    CP_COMMIT();

    const int nIter = K >> 5;
#pragma unroll 1
    for (int it = 0; it < nIter; it++) {
        if (it + 1 < nIter) {
            load_stage((it + 1) & 1, (it + 1) * 32);
            CP_COMMIT();
            CP_WAIT1();
        } else {
            CP_WAIT0();
        }
        __syncthreads();

        const uint32_t st = sb + (it & 1) * SSTAGE;
        const uint32_t sAh = st, sAl = st + SBUF, sBh = st + 2 * SBUF, sBl = st + 3 * SBUF;
#pragma unroll
        for (int ks = 0; ks < 2; ks++) {
            // A fragments: ldmatrix x4, tiles (rows0-7,k0)(rows8-15,k0)(rows0-7,k8)(rows8-15,k8)
            uint32_t ah[2][4], al[2][4];
            const uint32_t aoff = (uint32_t)(lane & 15) * SROW + ks * 32 + (lane >> 4) * 16;
#pragma unroll
            for (int mf = 0; mf < 2; mf++) {
                uint32_t base = (uint32_t)(wm * 32 + mf * 16) * SROW + aoff;
                LDM_X4(ah[mf][0], ah[mf][1], ah[mf][2], ah[mf][3], sAh + base);
                LDM_X4(al[mf][0], al[mf][1], al[mf][2], al[mf][3], sAl + base);
            }
            // B fragments: x4 covers two n8 frags (tiles nf0/k0, nf0/k8, nf1/k0, nf1/k8)
            uint32_t bh[8][2], bl[8][2];
            const uint32_t boff = (uint32_t)(lane & 7) * SROW + ks * 32 + ((lane >> 3) & 1) * 16 +
                                  (uint32_t)((lane >> 4)) * 8 * SROW;
#pragma unroll
            for (int np = 0; np < 4; np++) {
                uint32_t base = (uint32_t)(wn * 64 + np * 16) * SROW + boff;
                LDM_X4(bh[2 * np][0], bh[2 * np][1], bh[2 * np + 1][0], bh[2 * np + 1][1], sBh + base);
                LDM_X4(bl[2 * np][0], bl[2 * np][1], bl[2 * np + 1][0], bl[2 * np + 1][1], sBl + base);
            }
#pragma unroll
            for (int mf = 0; mf < 2; mf++)
#pragma unroll
                for (int nf = 0; nf < 8; nf++) {
                    MMA_BF16(acc[mf][nf], ah[mf], bh[nf]);
                    MMA_BF16(acc[mf][nf], ah[mf], bl[nf]);
                    MMA_BF16(acc[mf][nf], al[mf], bh[nf]);
                }
        }
        __syncthreads();
    }

    // --- epilogue ---
#pragma unroll
    for (int mf = 0; mf < 2; mf++) {
        int m = m0 + wm * 32 + mf * 16 + (lane >> 2);
#pragma unroll
        for (int nf = 0; nf < 8; nf++) {
            int n = n0 + wn * 64 + nf * 8 + (lane & 3) * 2;
            float* C = acc[mf][nf];
            if (EPI == 0) {
                *(float2*)(outF + (size_t)m * N + n) = make_float2(C[0], C[1]);
                *(float2*)(outF + (size_t)(m + 8) * N + n) = make_float2(C[2], C[3]);
            } else {
                float2 b = *(const float2*)(bias + n);
#pragma unroll
                for (int h = 0; h < 2; h++) {  // h=0: row m, h=1: row m+8
                    float v0 = fmaxf(C[2 * h] + b.x, 0.f);
                    float v1 = fmaxf(C[2 * h + 1] + b.y, 0.f);
                    __nv_bfloat16 h0 = __float2bfloat16(v0);
                    __nv_bfloat16 h1 = __float2bfloat16(v1);
                    __nv_bfloat16 l0 = __float2bfloat16(v0 - __bfloat162float(h0));
                    __nv_bfloat16 l1 = __float2bfloat16(v1 - __bfloat162float(h1));
                    size_t o = (size_t)(m + 8 * h) * N + n;
                    *(uint32_t*)(outH + o) = (uint32_t)__bfloat16_as_ushort(h0) |
                                             ((uint32_t)__bfloat16_as_ushort(h1) << 16);
                    *(uint32_t*)(outL + o) = (uint32_t)__bfloat16_as_ushort(l0) |
                                             ((uint32_t)__bfloat16_as_ushort(l1) << 16);
                }
            }
        }
    }
}

// ---------------- layer-3 aggregation (D=2) + bias + log_softmax ------------
__global__ void k_agg2_lsm(const float* __restrict__ in, float* __restrict__ out,
                           const float* __restrict__ b3) {
    int i = blockIdx.x * blockDim.x + threadIdx.x;
    if (i >= NN) return;
    float di = g_dinv[i];
    float sl = di * di;
    float2 v = *(const float2*)(in + 2 * (size_t)i);
    float a0 = sl * v.x, a1 = sl * v.y;
    int beg = g_rowptr[i], end = g_rowptr[i + 1];
    for (int e = beg; e < end; e++) {
        int s = g_csr_src[e];
        float w = g_csr_norm[e];
        float2 u = *(const float2*)(in + 2 * (size_t)s);
        a0 = fmaf(w, u.x, a0);
        a1 = fmaf(w, u.y, a1);
    }
    a0 += b3[0];
    a1 += b3[1];
    float m = fmaxf(a0, a1);
    float lse = m + logf(expf(a0 - m) + expf(a1 - m));
    out[2 * (size_t)i + 0] = a0 - lse;
    out[2 * (size_t)i + 1] = a1 - lse;
}

// ---------------- launch -----------------------------------------------------
extern "C" void kernel_launch(void* const* d_in, const int* in_sizes, int n_in,
                              void* d_out, int out_size) {
    const float* x  = (const float*)d_in[0];
    const float* W1 = (const float*)d_in[1];
    const float* b1 = (const float*)d_in[2];
    const float* W2 = (const float*)d_in[3];
    const float* b2 = (const float*)d_in[4];
    const float* W3 = (const float*)d_in[5];
    const float* b3 = (const float*)d_in[6];
    const void*  ei = d_in[7];
    float* out = (float*)d_out;

    void* p;
    cudaGetSymbolAddress(&p, g_axh); __nv_bfloat16* axh = (__nv_bfloat16*)p;
    cudaGetSymbolAddress(&p, g_axl); __nv_bfloat16* axl = (__nv_bfloat16*)p;
    cudaGetSymbolAddress(&p, g_h1h); __nv_bfloat16* h1h = (__nv_bfloat16*)p;
    cudaGetSymbolAddress(&p, g_h1l); __nv_bfloat16* h1l = (__nv_bfloat16*)p;
    cudaGetSymbolAddress(&p, g_t2);  float* t2 = (float*)p;
    cudaGetSymbolAddress(&p, g_t3);  float* t3 = (float*)p;
    cudaGetSymbolAddress(&p, g_w1h); __nv_bfloat16* w1h = (__nv_bfloat16*)p;
    cudaGetSymbolAddress(&p, g_w1l); __nv_bfloat16* w1l = (__nv_bfloat16*)p;
    cudaGetSymbolAddress(&p, g_w2h); __nv_bfloat16* w2h = (__nv_bfloat16*)p;
    cudaGetSymbolAddress(&p, g_w2l); __nv_bfloat16* w2l = (__nv_bfloat16*)p;

    cudaFuncSetAttribute(k_hmma<128, 256, 1>, cudaFuncAttributeMaxDynamicSharedMemorySize, SMEM_TOTAL);
    cudaFuncSetAttribute(k_hmma<256, 128, 0>, cudaFuncAttributeMaxDynamicSharedMemorySize, SMEM_TOTAL);

    // graph preprocessing
    k_detect<<<1, 256>>>((const int*)ei);
    k_initdeg<<<(NN + 255) / 256, 256>>>();
    k_convert<<<(NE + 255) / 256, 256>>>(ei);
    k_dinv<<<(NN + 255) / 256, 256>>>();
    k_scan1<<<NCHUNK, 1024>>>();
    k_scan2<<<1, 32>>>();
    k_scan3<<<(NN + 1023) / 1024, 1024>>>();
    k_scatter<<<(NE + 255) / 256, 256>>>();

    // weight splits
    k_wsplit<<<(128 * 256 + 255) / 256, 256>>>(W1, w1h, w1l, 128, 256);
    k_wsplit<<<(256 * 128 + 255) / 256, 256>>>(W2, w2h, w2l, 256, 128);

    const int aggBlocks = (NN * 32 + 255) / 256;
    const int mTiles = NP / 128;  // 391

    // Layer 1: agg(x) -> split -> HMMA GEMM (+b1, relu, split out)
    k_agg128_split<<<aggBlocks, 256>>>(x, axh, axl);
    k_hmma<128, 256, 1><<<dim3(2, mTiles), 256, SMEM_TOTAL>>>(axh, axl, w1h, w1l, b1, nullptr, h1h, h1l);

    // Layer 2: h1 @ W2 (HMMA) -> agg (+b2, relu) fused with W3 projection
    k_hmma<256, 128, 0><<<dim3(1, mTiles), 256, SMEM_TOTAL>>>(h1h, h1l, w2h, w2l, nullptr, t2, nullptr, nullptr);
    k_agg128_g3<<<aggBlocks, 256>>>(t2, t3, b2, W3);

    // Layer 3: agg(t3) -> +b3 -> log_softmax
    k_agg2_lsm<<<(NN + 255) / 256, 256>>>(t3, out, b3);
}

// round 10
// speedup vs baseline: 2.0108x; 1.5108x over previous
#include <cuda_runtime.h>
#include <cuda_bf16.h>
#include <math.h>
#include <stdint.h>

#define NN 50000
#define NP 50048   // 391 * 128, padded M
#define NE 600000
#define NCHUNK 49  // ceil(NN/1024)

// ---------------- scratch (static device globals; zero-initialized) ---------
__device__ int   g_is64;
__device__ int   g_src[NE];
__device__ int   g_dst[NE];
__device__ int   g_deg[NN];
__device__ float g_dinv[NN];
__device__ int   g_rowptr[NN + 1];
__device__ int   g_rowcur[NN];
__device__ int   g_psum[NCHUNK];
__device__ int   g_csr_src[NE];
__device__ float g_csr_norm[NE];

__device__ __nv_bfloat16 g_axh[(size_t)NP * 128];
__device__ __nv_bfloat16 g_axl[(size_t)NP * 128];
__device__ __nv_bfloat16 g_h1h[(size_t)NP * 256];
__device__ __nv_bfloat16 g_h1l[(size_t)NP * 256];
__device__ float g_t2[(size_t)NP * 128];
__device__ float g_t3[(size_t)NN * 2];
__device__ __nv_bfloat16 g_w1h[256 * 128], g_w1l[256 * 128];   // W1^T hi/lo [N=256][K=128]
__device__ __nv_bfloat16 g_w2h[128 * 256], g_w2l[128 * 256];   // W2^T hi/lo [N=128][K=256]

// ---------------- small PTX helpers (all <= sm_80 features) ------------------
__device__ __forceinline__ uint32_t smem_u32(const void* p) {
    uint32_t a;
    asm("{ .reg .u64 t; cvta.to.shared.u64 t, %1; cvt.u32.u64 %0, t; }" : "=r"(a) : "l"(p));
    return a;
}
__device__ __forceinline__ void cp16(uint32_t dst, const void* src) {
    asm volatile("cp.async.cg.shared.global [%0], [%1], 16;" :: "r"(dst), "l"(src));
}
#define CP_COMMIT() asm volatile("cp.async.commit_group;" ::: "memory")
#define CP_WAIT0()  asm volatile("cp.async.wait_group 0;" ::: "memory")
#define CP_WAIT1()  asm volatile("cp.async.wait_group 1;" ::: "memory")

#define LDM_X4(r0, r1, r2, r3, a) \
    asm volatile("ldmatrix.sync.aligned.m8n8.x4.shared.b16 {%0,%1,%2,%3}, [%4];" \
                 : "=r"(r0), "=r"(r1), "=r"(r2), "=r"(r3) : "r"(a))

#define MMA_BF16(C, A, B) \
    asm volatile("mma.sync.aligned.m16n8k16.row.col.f32.bf16.bf16.f32 " \
                 "{%0,%1,%2,%3},{%4,%5,%6,%7},{%8,%9},{%0,%1,%2,%3};" \
                 : "+f"((C)[0]), "+f"((C)[1]), "+f"((C)[2]), "+f"((C)[3]) \
                 : "r"((A)[0]), "r"((A)[1]), "r"((A)[2]), "r"((A)[3]), \
                   "r"((B)[0]), "r"((B)[1]))

// ---------------- fused init: deg=1, is64 detect, weight transpose+split ----
__global__ void k_init(const int* __restrict__ e32, const float* __restrict__ W1,
                       const float* __restrict__ W2) {
    int i = blockIdx.x * blockDim.x + threadIdx.x;
    if (i < NN) g_deg[i] = 1;  // self-loop
    if (i < 128 * 256) {                 // W1 [128][256] -> W1^T [256][128]
        int k = i / 256, n = i % 256;
        float v = W1[i];
        __nv_bfloat16 h = __float2bfloat16(v);
        g_w1h[n * 128 + k] = h;
        g_w1l[n * 128 + k] = __float2bfloat16(v - __bfloat162float(h));
    } else if (i < 2 * 128 * 256) {      // W2 [256][128] -> W2^T [128][256]
        int j = i - 128 * 256;
        int k = j / 128, n = j % 128;
        float v = W2[j];
        __nv_bfloat16 h = __float2bfloat16(v);
        g_w2h[n * 256 + k] = h;
        g_w2l[n * 256 + k] = __float2bfloat16(v - __bfloat162float(h));
    }
    if (blockIdx.x == 0) {
        __shared__ int s;
        if (threadIdx.x == 0) s = 0;
        __syncthreads();
        int nz = 0;
        for (int j = threadIdx.x; j < 1000; j += blockDim.x)
            if (e32[2 * j + 1] != 0) nz = 1;
        if (nz) atomicExch(&s, 1);
        __syncthreads();
        if (threadIdx.x == 0) g_is64 = (s == 0) ? 1 : 0;
    }
}

__global__ void k_convert(const void* __restrict__ e) {
    int i = blockIdx.x * blockDim.x + threadIdx.x;
    if (i >= NE) return;
    int s, d;
    if (g_is64) {
        const long long* p = (const long long*)e;
        s = (int)p[i];
        d = (int)p[NE + i];
    } else {
        const int* p = (const int*)e;
        s = p[i];
        d = p[NE + i];
    }
    g_src[i] = s;
    g_dst[i] = d;
    atomicAdd(&g_deg[d], 1);
}

// fused: per-chunk scan of (deg-1) + dinv = rsqrt(deg)
__global__ void k_scan1() {
    __shared__ int sh[1024];
    int b = blockIdx.x;
    int i = b * 1024 + threadIdx.x;
    int dg = (i < NN) ? g_deg[i] : 1;
    if (i < NN) g_dinv[i] = rsqrtf((float)dg);
    int v = dg - 1;
    sh[threadIdx.x] = v;
    __syncthreads();
    for (int off = 1; off < 1024; off <<= 1) {
        int t = (threadIdx.x >= off) ? sh[threadIdx.x - off] : 0;
        __syncthreads();
        sh[threadIdx.x] += t;
        __syncthreads();
    }
    if (i < NN) g_rowptr[i] = sh[threadIdx.x] - v;  // local exclusive
    if (threadIdx.x == 1023) g_psum[b] = sh[1023];
}

// each block sums its own chunk-offset prefix (49 adds) — no separate scan2
__global__ void k_scan3() {
    __shared__ int off;
    if (threadIdx.x == 0) {
        int r = 0;
        for (int j = 0; j < (int)blockIdx.x; j++) r += g_psum[j];
        off = r;
    }
    __syncthreads();
    int i = blockIdx.x * 1024 + threadIdx.x;
    if (i < NN) {
        int r = g_rowptr[i] + off;
        g_rowptr[i] = r;
        g_rowcur[i] = r;
    }
    if (i == 0) g_rowptr[NN] = NE;
}

__global__ void k_scatter() {
    int e = blockIdx.x * blockDim.x + threadIdx.x;
    if (e >= NE) return;
    int d = g_dst[e];
    int s = g_src[e];
    int pos = atomicAdd(&g_rowcur[d], 1);
    g_csr_src[pos] = s;
    g_csr_norm[pos] = g_dinv[s] * g_dinv[d];
}

// ---------------- layer-2 aggregation + bias/relu + fused W3 projection -----
__global__ void k_agg128_g3(const float* __restrict__ in, float* __restrict__ out,
                            const float* __restrict__ bias, const float* __restrict__ W3) {
    __shared__ float w[256];
    if (threadIdx.x < 256) w[threadIdx.x] = W3[threadIdx.x];
    __syncthreads();
    int node = (blockIdx.x * blockDim.x + threadIdx.x) >> 5;
    if (node >= NN) return;
    int lane = threadIdx.x & 31;
    float di = g_dinv[node];
    float sl = di * di;
    float4 acc = __ldg((const float4*)(in + (size_t)node * 128) + lane);
    acc.x *= sl; acc.y *= sl; acc.z *= sl; acc.w *= sl;
    int beg = g_rowptr[node], end = g_rowptr[node + 1];
    for (int e = beg; e < end; e++) {
        int s = g_csr_src[e];
        float wgt = g_csr_norm[e];
        float4 v = __ldg((const float4*)(in + (size_t)s * 128) + lane);
        acc.x = fmaf(wgt, v.x, acc.x);
        acc.y = fmaf(wgt, v.y, acc.y);
        acc.z = fmaf(wgt, v.z, acc.z);
        acc.w = fmaf(wgt, v.w, acc.w);
    }
    float4 b = ((const float4*)bias)[lane];
    acc.x = fmaxf(acc.x + b.x, 0.f);
    acc.y = fmaxf(acc.y + b.y, 0.f);
    acc.z = fmaxf(acc.z + b.z, 0.f);
    acc.w = fmaxf(acc.w + b.w, 0.f);
    float a0 = acc.x * w[8 * lane + 0] + acc.y * w[8 * lane + 2] +
               acc.z * w[8 * lane + 4] + acc.w * w[8 * lane + 6];
    float a1 = acc.x * w[8 * lane + 1] + acc.y * w[8 * lane + 3] +
               acc.z * w[8 * lane + 5] + acc.w * w[8 * lane + 7];
#pragma unroll
    for (int o = 16; o > 0; o >>= 1) {
        a0 += __shfl_xor_sync(0xffffffffu, a0, o);
        a1 += __shfl_xor_sync(0xffffffffu, a1, o);
    }
    if (lane == 0) {
        out[2 * (size_t)node + 0] = a0;
        out[2 * (size_t)node + 1] = a1;
    }
}

// ---------------- layer-1 input aggregation -> bf16 hi/lo split --------------
__global__ void k_agg128_split(const float* __restrict__ in, __nv_bfloat16* __restrict__ oh,
                               __nv_bfloat16* __restrict__ ol) {
    int node = (blockIdx.x * blockDim.x + threadIdx.x) >> 5;
    if (node >= NN) return;
    int lane = threadIdx.x & 31;
    float di = g_dinv[node];
    float sl = di * di;
    float4 acc = __ldg((const float4*)(in + (size_t)node * 128) + lane);
    acc.x *= sl; acc.y *= sl; acc.z *= sl; acc.w *= sl;
    int beg = g_rowptr[node], end = g_rowptr[node + 1];
    for (int e = beg; e < end; e++) {
        int s = g_csr_src[e];
        float w = g_csr_norm[e];
        float4 v = __ldg((const float4*)(in + (size_t)s * 128) + lane);
        acc.x = fmaf(w, v.x, acc.x);
        acc.y = fmaf(w, v.y, acc.y);
        acc.z = fmaf(w, v.z, acc.z);
        acc.w = fmaf(w, v.w, acc.w);
    }
    float a[4] = {acc.x, acc.y, acc.z, acc.w};
    unsigned short hs[4], ls[4];
#pragma unroll
    for (int j = 0; j < 4; j++) {
        __nv_bfloat16 h = __float2bfloat16(a[j]);
        float r = a[j] - __bfloat162float(h);
        hs[j] = __bfloat16_as_ushort(h);
        ls[j] = __bfloat16_as_ushort(__float2bfloat16(r));
    }
    size_t off = (size_t)node * 128 + lane * 4;
    *(uint2*)(oh + off) = make_uint2((uint32_t)hs[0] | ((uint32_t)hs[1] << 16),
                                     (uint32_t)hs[2] | ((uint32_t)hs[3] << 16));
    *(uint2*)(ol + off) = make_uint2((uint32_t)ls[0] | ((uint32_t)ls[1] << 16),
                                     (uint32_t)ls[2] | ((uint32_t)ls[3] << 16));
}

// ---------------- split-bf16 HMMA GEMM (unchanged, proven correct) -----------
#define SROW 80        // bytes per smem row (32 bf16 + 16B pad)
#define SBUF 10240     // 128 rows * 80B, one matrix, one stage
#define SSTAGE 40960   // 4 matrices
#define SMEM_TOTAL 81920

template <int K, int N, int EPI>
__global__ void __launch_bounds__(256)
k_hmma(const __nv_bfloat16* __restrict__ Ah, const __nv_bfloat16* __restrict__ Al,
       const __nv_bfloat16* __restrict__ Bh, const __nv_bfloat16* __restrict__ Bl,
       const float* __restrict__ bias, float* __restrict__ outF,
       __nv_bfloat16* __restrict__ outH, __nv_bfloat16* __restrict__ outL) {
    extern __shared__ char smem[];
    const uint32_t sb = smem_u32(smem);
    const int tid = threadIdx.x;
    const int lane = tid & 31;
    const int warp = tid >> 5;
    const int wm = warp & 3;
    const int wn = warp >> 2;
    const int m0 = blockIdx.y * 128;
    const int n0 = blockIdx.x * 128;

    const __nv_bfloat16* gsrc[4] = {Ah, Al, Bh, Bl};

    float acc[2][8][4];
#pragma unroll
    for (int i = 0; i < 2; i++)
#pragma unroll
        for (int j = 0; j < 8; j++)
#pragma unroll
            for (int c = 0; c < 4; c++) acc[i][j][c] = 0.f;

    auto load_stage = [&](int stage, int kk0) {
#pragma unroll
        for (int j = 0; j < 8; j++) {
            int c = tid + j * 256;
            int which = c >> 9;
            int cc = c & 511;
            int row = cc >> 2, kc = cc & 3;
            int grow = (which < 2) ? (m0 + row) : (n0 + row);
            const __nv_bfloat16* src = gsrc[which] + (size_t)grow * K + kk0 + kc * 8;
            uint32_t dst = sb + stage * SSTAGE + which * SBUF + row * SROW + kc * 16;
            cp16(dst, src);
        }
    };

    load_stage(0, 0);
    CP_COMMIT();

    const int nIter = K >> 5;
#pragma unroll 1
    for (int it = 0; it < nIter; it++) {
        if (it + 1 < nIter) {
            load_stage((it + 1) & 1, (it + 1) * 32);
            CP_COMMIT();
            CP_WAIT1();
        } else {
            CP_WAIT0();
        }
        __syncthreads();

        const uint32_t st = sb + (it & 1) * SSTAGE;
        const uint32_t sAh = st, sAl = st + SBUF, sBh = st + 2 * SBUF, sBl = st + 3 * SBUF;
#pragma unroll
        for (int ks = 0; ks < 2; ks++) {
            uint32_t ah[2][4], al[2][4];
            const uint32_t aoff = (uint32_t)(lane & 15) * SROW + ks * 32 + (lane >> 4) * 16;
#pragma unroll
            for (int mf = 0; mf < 2; mf++) {
                uint32_t base = (uint32_t)(wm * 32 + mf * 16) * SROW + aoff;
                LDM_X4(ah[mf][0], ah[mf][1], ah[mf][2], ah[mf][3], sAh + base);
                LDM_X4(al[mf][0], al[mf][1], al[mf][2], al[mf][3], sAl + base);
            }
            uint32_t bh[8][2], bl[8][2];
            const uint32_t boff = (uint32_t)(lane & 7) * SROW + ks * 32 + ((lane >> 3) & 1) * 16 +
                                  (uint32_t)((lane >> 4)) * 8 * SROW;
#pragma unroll
            for (int np = 0; np < 4; np++) {
                uint32_t base = (uint32_t)(wn * 64 + np * 16) * SROW + boff;
                LDM_X4(bh[2 * np][0], bh[2 * np][1], bh[2 * np + 1][0], bh[2 * np + 1][1], sBh + base);
                LDM_X4(bl[2 * np][0], bl[2 * np][1], bl[2 * np + 1][0], bl[2 * np + 1][1], sBl + base);
            }
#pragma unroll
            for (int mf = 0; mf < 2; mf++)
#pragma unroll
                for (int nf = 0; nf < 8; nf++) {
                    MMA_BF16(acc[mf][nf], ah[mf], bh[nf]);
                    MMA_BF16(acc[mf][nf], ah[mf], bl[nf]);
                    MMA_BF16(acc[mf][nf], al[mf], bh[nf]);
                }
        }
        __syncthreads();
    }

#pragma unroll
    for (int mf = 0; mf < 2; mf++) {
        int m = m0 + wm * 32 + mf * 16 + (lane >> 2);
#pragma unroll
        for (int nf = 0; nf < 8; nf++) {
            int n = n0 + wn * 64 + nf * 8 + (lane & 3) * 2;
            float* C = acc[mf][nf];
            if (EPI == 0) {
                *(float2*)(outF + (size_t)m * N + n) = make_float2(C[0], C[1]);
                *(float2*)(outF + (size_t)(m + 8) * N + n) = make_float2(C[2], C[3]);
            } else {
                float2 b = *(const float2*)(bias + n);
#pragma unroll
                for (int h = 0; h < 2; h++) {
                    float v0 = fmaxf(C[2 * h] + b.x, 0.f);
                    float v1 = fmaxf(C[2 * h + 1] + b.y, 0.f);
                    __nv_bfloat16 h0 = __float2bfloat16(v0);
                    __nv_bfloat16 h1 = __float2bfloat16(v1);
                    __nv_bfloat16 l0 = __float2bfloat16(v0 - __bfloat162float(h0));
                    __nv_bfloat16 l1 = __float2bfloat16(v1 - __bfloat162float(h1));
                    size_t o = (size_t)(m + 8 * h) * N + n;
                    *(uint32_t*)(outH + o) = (uint32_t)__bfloat16_as_ushort(h0) |
                                             ((uint32_t)__bfloat16_as_ushort(h1) << 16);
                    *(uint32_t*)(outL + o) = (uint32_t)__bfloat16_as_ushort(l0) |
                                             ((uint32_t)__bfloat16_as_ushort(l1) << 16);
                }
            }
        }
    }
}

// ---------------- layer-3 aggregation (D=2) + bias + log_softmax ------------
__global__ void k_agg2_lsm(const float* __restrict__ in, float* __restrict__ out,
                           const float* __restrict__ b3) {
    int i = blockIdx.x * blockDim.x + threadIdx.x;
    if (i >= NN) return;
    float di = g_dinv[i];
    float sl = di * di;
    float2 v = *(const float2*)(in + 2 * (size_t)i);
    float a0 = sl * v.x, a1 = sl * v.y;
    int beg = g_rowptr[i], end = g_rowptr[i + 1];
    for (int e = beg; e < end; e++) {
        int s = g_csr_src[e];
        float w = g_csr_norm[e];
        float2 u = *(const float2*)(in + 2 * (size_t)s);
        a0 = fmaf(w, u.x, a0);
        a1 = fmaf(w, u.y, a1);
    }
    a0 += b3[0];
    a1 += b3[1];
    float m = fmaxf(a0, a1);
    float lse = m + logf(expf(a0 - m) + expf(a1 - m));
    out[2 * (size_t)i + 0] = a0 - lse;
    out[2 * (size_t)i + 1] = a1 - lse;
}

// ---------------- launch -----------------------------------------------------
extern "C" void kernel_launch(void* const* d_in, const int* in_sizes, int n_in,
                              void* d_out, int out_size) {
    const float* x  = (const float*)d_in[0];
    const float* W1 = (const float*)d_in[1];
    const float* b1 = (const float*)d_in[2];
    const float* W2 = (const float*)d_in[3];
    const float* b2 = (const float*)d_in[4];
    const float* W3 = (const float*)d_in[5];
    const float* b3 = (const float*)d_in[6];
    const void*  ei = d_in[7];
    float* out = (float*)d_out;

    void* p;
    cudaGetSymbolAddress(&p, g_axh); __nv_bfloat16* axh = (__nv_bfloat16*)p;
    cudaGetSymbolAddress(&p, g_axl); __nv_bfloat16* axl = (__nv_bfloat16*)p;
    cudaGetSymbolAddress(&p, g_h1h); __nv_bfloat16* h1h = (__nv_bfloat16*)p;
    cudaGetSymbolAddress(&p, g_h1l); __nv_bfloat16* h1l = (__nv_bfloat16*)p;
    cudaGetSymbolAddress(&p, g_t2);  float* t2 = (float*)p;
    cudaGetSymbolAddress(&p, g_t3);  float* t3 = (float*)p;
    cudaGetSymbolAddress(&p, g_w1h); __nv_bfloat16* w1h = (__nv_bfloat16*)p;
    cudaGetSymbolAddress(&p, g_w1l); __nv_bfloat16* w1l = (__nv_bfloat16*)p;
    cudaGetSymbolAddress(&p, g_w2h); __nv_bfloat16* w2h = (__nv_bfloat16*)p;
    cudaGetSymbolAddress(&p, g_w2l); __nv_bfloat16* w2l = (__nv_bfloat16*)p;

    cudaFuncSetAttribute(k_hmma<128, 256, 1>, cudaFuncAttributeMaxDynamicSharedMemorySize, SMEM_TOTAL);
    cudaFuncSetAttribute(k_hmma<256, 128, 0>, cudaFuncAttributeMaxDynamicSharedMemorySize, SMEM_TOTAL);

    // graph preprocessing + weight split (merged: 5 launches)
    k_init<<<(2 * 128 * 256 + 255) / 256, 256>>>((const int*)ei, W1, W2);
    k_convert<<<(NE + 255) / 256, 256>>>(ei);
    k_scan1<<<NCHUNK, 1024>>>();
    k_scan3<<<NCHUNK, 1024>>>();
    k_scatter<<<(NE + 255) / 256, 256>>>();

    const int aggBlocks = (NN * 32 + 255) / 256;
    const int mTiles = NP / 128;  // 391

    // Layer 1: agg(x) -> split -> HMMA GEMM (+b1, relu, split out)
    k_agg128_split<<<aggBlocks, 256>>>(x, axh, axl);
    k_hmma<128, 256, 1><<<dim3(2, mTiles), 256, SMEM_TOTAL>>>(axh, axl, w1h, w1l, b1, nullptr, h1h, h1l);

    // Layer 2: h1 @ W2 (HMMA) -> agg (+b2, relu) fused with W3 projection
    k_hmma<256, 128, 0><<<dim3(1, mTiles), 256, SMEM_TOTAL>>>(h1h, h1l, w2h, w2l, nullptr, t2, nullptr, nullptr);
    k_agg128_g3<<<aggBlocks, 256>>>(t2, t3, b2, W3);

    // Layer 3: agg(t3) -> +b3 -> log_softmax
    k_agg2_lsm<<<(NN + 255) / 256, 256>>>(t3, out, b3);
}